// round 6
// baseline (speedup 1.0000x reference)
#include <cuda_runtime.h>
#include <cstdint>

// LinearCRF: out = mean_b( logZ_b - gold_b )
// 256 threads/block, 4 rows/block, 2 warps per row, lane = 16 steps.
// cp.async staging into transposed conflict-free smem; tags+mask packed
// to 1 byte/step. Linear-domain 3x3 transfer matrices, exact pow2 renorm.
// FAST path (runtime-guarded): transitions == reference constants ->
// unit-diagonal E with immediate-operand FMAs + unconditional masked math.
// Generic fallback path preserves full semantics for arbitrary inputs.

#define B_DIM   8192
#define L_DIM   1024
#define RPB     4
#define THREADS 256
#define NBLOCKS (B_DIM / RPB)      // 2048
#define LN2F 0.69314718055994530942f
#define AF 2.71828182845904523536f     // e^1
#define BF 0.00673794699908546710f     // e^-5

#define EM_F4_PER_ROW 768
#define SMEM_BYTES (RPB * EM_F4_PER_ROW * 16 + RPB * 256 * 4)

__device__ float g_partials[NBLOCKS];
__device__ int   g_count = 0;

__device__ __forceinline__ void cp16(uint32_t saddr, const void* gaddr) {
    asm volatile("cp.async.cg.shared.global [%0], [%1], 16;" :: "r"(saddr), "l"(gaddr));
}

// ---------- FAST path: E = [[1,a,b],[a,1,a],[b,a,1]], T in {0,1,-5} ----------
// Unconditional step (mask known set).
#define STEP_FAST_U(e0v, e1v, e2v, cbv) do {                                \
    float w0 = __expf(e0v), w1 = __expf(e1v), w2 = __expf(e2v);             \
    float s0 = M00 + M02, s1 = M10 + M12, s2 = M20 + M22;                   \
    float P00 = fmaf(AF, M01, fmaf(BF, M02, M00));                          \
    float P01 = fmaf(AF, s0, M01);                                          \
    float P02 = fmaf(BF, M00, fmaf(AF, M01, M02));                          \
    float P10 = fmaf(AF, M11, fmaf(BF, M12, M10));                          \
    float P11 = fmaf(AF, s1, M11);                                          \
    float P12 = fmaf(BF, M10, fmaf(AF, M11, M12));                          \
    float P20 = fmaf(AF, M21, fmaf(BF, M22, M20));                          \
    float P21 = fmaf(AF, s2, M21);                                          \
    float P22 = fmaf(BF, M20, fmaf(AF, M21, M22));                          \
    M00 = P00 * w0; M01 = P01 * w1; M02 = P02 * w2;                         \
    M10 = P10 * w0; M11 = P11 * w1; M12 = P12 * w2;                         \
    M20 = P20 * w0; M21 = P21 * w1; M22 = P22 * w2;                         \
    int tgl = (int)((cbv) & 3u);                                            \
    float etg = (tgl == 0) ? (e0v) : ((tgl == 1) ? (e1v) : (e2v));          \
    float tr  = (ptag == tgl) ? 0.f : ((ptag + tgl == 2) ? -5.f : 1.f);     \
    gold += tr + etg;                                                       \
    ptag = tgl;                                                             \
} while (0)

// Masked step (rare: init step / mask==0 data).
#define STEP_FAST_M(e0v, e1v, e2v, cbv) do {                                \
    unsigned cb_ = (cbv) & 0xffu;                                           \
    float w0 = __expf(e0v), w1 = __expf(e1v), w2 = __expf(e2v);             \
    float s0 = M00 + M02, s1 = M10 + M12, s2 = M20 + M22;                   \
    float P00 = fmaf(AF, M01, fmaf(BF, M02, M00));                          \
    float P01 = fmaf(AF, s0, M01);                                          \
    float P02 = fmaf(BF, M00, fmaf(AF, M01, M02));                          \
    float P10 = fmaf(AF, M11, fmaf(BF, M12, M10));                          \
    float P11 = fmaf(AF, s1, M11);                                          \
    float P12 = fmaf(BF, M10, fmaf(AF, M11, M12));                          \
    float P20 = fmaf(AF, M21, fmaf(BF, M22, M20));                          \
    float P21 = fmaf(AF, s2, M21);                                          \
    float P22 = fmaf(BF, M20, fmaf(AF, M21, M22));                          \
    bool u = cb_ >= 4u;                                                     \
    M00 = u ? P00 * w0 : M00; M01 = u ? P01 * w1 : M01;                     \
    M02 = u ? P02 * w2 : M02;                                               \
    M10 = u ? P10 * w0 : M10; M11 = u ? P11 * w1 : M11;                     \
    M12 = u ? P12 * w2 : M12;                                               \
    M20 = u ? P20 * w0 : M20; M21 = u ? P21 * w1 : M21;                     \
    M22 = u ? P22 * w2 : M22;                                               \
    int tgl = (int)(cb_ & 3u);                                              \
    float etg = (tgl == 0) ? (e0v) : ((tgl == 1) ? (e1v) : (e2v));          \
    float tr  = (ptag == tgl) ? 0.f : ((ptag + tgl == 2) ? -5.f : 1.f);     \
    gold += u ? (tr + etg) : 0.f;                                           \
    ptag = tgl;                                                             \
} while (0)

#define GROUP_FAST(Ea, Eb, Ec, CW) do {                                     \
    if (((CW) & 0x04040404u) == 0x04040404u) {                              \
        STEP_FAST_U(Ea.x, Ea.y, Ea.z, (CW));                                \
        STEP_FAST_U(Ea.w, Eb.x, Eb.y, (CW) >> 8);                           \
        STEP_FAST_U(Eb.z, Eb.w, Ec.x, (CW) >> 16);                          \
        STEP_FAST_U(Ec.y, Ec.z, Ec.w, (CW) >> 24);                          \
    } else {                                                                \
        STEP_FAST_M(Ea.x, Ea.y, Ea.z, (CW));                                \
        STEP_FAST_M(Ea.w, Eb.x, Eb.y, (CW) >> 8);                           \
        STEP_FAST_M(Eb.z, Eb.w, Ec.x, (CW) >> 16);                          \
        STEP_FAST_M(Ec.y, Ec.z, Ec.w, (CW) >> 24);                          \
    }                                                                       \
} while (0)

// ---------- generic fallback step ----------
#define STEP_GEN(e0v, e1v, e2v, cbv) do {                                   \
    unsigned cb_ = (cbv) & 0xffu;                                           \
    float w0 = __expf(e0v), w1 = __expf(e1v), w2 = __expf(e2v);             \
    float F00 = E00 * w0, F01 = E01 * w1, F02 = E02 * w2;                   \
    float F10 = E10 * w0, F11 = E11 * w1, F12 = E12 * w2;                   \
    float F20 = E20 * w0, F21 = E21 * w1, F22 = E22 * w2;                   \
    float n00 = fmaf(M02, F20, fmaf(M01, F10, M00 * F00));                  \
    float n01 = fmaf(M02, F21, fmaf(M01, F11, M00 * F01));                  \
    float n02 = fmaf(M02, F22, fmaf(M01, F12, M00 * F02));                  \
    float n10 = fmaf(M12, F20, fmaf(M11, F10, M10 * F00));                  \
    float n11 = fmaf(M12, F21, fmaf(M11, F11, M10 * F01));                  \
    float n12 = fmaf(M12, F22, fmaf(M11, F12, M10 * F02));                  \
    float n20 = fmaf(M22, F20, fmaf(M21, F10, M20 * F00));                  \
    float n21 = fmaf(M22, F21, fmaf(M21, F11, M20 * F01));                  \
    float n22 = fmaf(M22, F22, fmaf(M21, F12, M20 * F02));                  \
    bool u = cb_ >= 4u;                                                     \
    M00 = u ? n00 : M00; M01 = u ? n01 : M01; M02 = u ? n02 : M02;          \
    M10 = u ? n10 : M10; M11 = u ? n11 : M11; M12 = u ? n12 : M12;          \
    M20 = u ? n20 : M20; M21 = u ? n21 : M21; M22 = u ? n22 : M22;          \
    int tgl = (int)(cb_ & 3u);                                              \
    float etg = (tgl == 0) ? (e0v) : ((tgl == 1) ? (e1v) : (e2v));          \
    float add = sT[ptag * 3 + tgl] + etg;                                   \
    gold += u ? add : 0.f;                                                  \
    ptag = tgl;                                                             \
} while (0)

#define GROUP_GEN(Ea, Eb, Ec, CW) do {                                      \
    STEP_GEN(Ea.x, Ea.y, Ea.z, (CW));                                       \
    STEP_GEN(Ea.w, Eb.x, Eb.y, (CW) >> 8);                                  \
    STEP_GEN(Eb.z, Eb.w, Ec.x, (CW) >> 16);                                 \
    STEP_GEN(Ec.y, Ec.z, Ec.w, (CW) >> 24);                                 \
} while (0)

#define RENORM() do {                                                       \
    float mxa = fmaxf(fmaxf(M00, M01), M02);                                \
    float mxb = fmaxf(fmaxf(M10, M11), M12);                                \
    float mxc = fmaxf(fmaxf(M20, M21), M22);                                \
    float mx  = fmaxf(fmaxf(mxa, mxb), mxc);                                \
    int ex = (__float_as_int(mx) >> 23) - 127;                              \
    float sc = __int_as_float((127 - ex) << 23);                            \
    M00 *= sc; M01 *= sc; M02 *= sc;                                        \
    M10 *= sc; M11 *= sc; M12 *= sc;                                        \
    M20 *= sc; M21 *= sc; M22 *= sc;                                        \
    esum += ex;                                                             \
} while (0)

__global__ void __launch_bounds__(THREADS)
crf_main_kernel(const float* __restrict__ emissions,
                const float* __restrict__ mask,
                const float* __restrict__ transitions,
                const int*   __restrict__ tags,
                float* __restrict__ out)
{
    extern __shared__ char smem[];
    float4*   emS    = (float4*)smem;
    unsigned* codesS = (unsigned*)(smem + RPB * EM_F4_PER_ROW * 16);
    __shared__ float sT[9];
    __shared__ float sHalf[8][11];
    __shared__ float srow[RPB];
    __shared__ int   sLast;

    const int tid  = threadIdx.x;
    const int lane = tid & 31;
    const int w    = tid >> 5;      // 0..7
    const int r    = w >> 1;        // local row
    const int h    = w & 1;         // half
    const int row0 = blockIdx.x * RPB;

    if (tid < 9) sT[tid] = transitions[tid];

    uint32_t emS_a = (uint32_t)__cvta_generic_to_shared(emS);

    // ---- stage emissions: gmem-linear f4 -> smem transposed (j*64 + owner) ----
    const float4* emG = (const float4*)emissions + (size_t)row0 * 768;
    #pragma unroll
    for (int rr = 0; rr < RPB; ++rr) {
        #pragma unroll
        for (int i = 0; i < 3; ++i) {
            int k = tid + i * THREADS;              // 0..767
            int o = k / 12, j = k - o * 12;
            cp16(emS_a + (uint32_t)((rr * EM_F4_PER_ROW + j * 64 + o) << 4),
                 emG + (size_t)rr * 768 + k);
        }
    }
    asm volatile("cp.async.commit_group;");

    // ---- pack tags+mask into code bytes ----
    const int4*   tgG = (const int4*)tags + (size_t)row0 * 256;
    const float4* mkG = (const float4*)mask + (size_t)row0 * 256;
    #pragma unroll
    for (int rr = 0; rr < RPB; ++rr) {
        int4   tg = tgG[(size_t)rr * 256 + tid];
        float4 mk = mkG[(size_t)rr * 256 + tid];
        unsigned cw = ((unsigned)(tg.x & 3) | (mk.x > 0.f ? 4u : 0u))
                    | (((unsigned)(tg.y & 3) | (mk.y > 0.f ? 4u : 0u)) << 8)
                    | (((unsigned)(tg.z & 3) | (mk.z > 0.f ? 4u : 0u)) << 16)
                    | (((unsigned)(tg.w & 3) | (mk.w > 0.f ? 4u : 0u)) << 24);
        codesS[rr * 256 + tid] = cw;
    }
    asm volatile("cp.async.wait_group 0;");
    __syncthreads();

    // runtime guard: does transitions match the specialized constants?
    bool fastpath = (sT[0] == 0.f && sT[1] == 1.f && sT[2] == -5.f &&
                     sT[3] == 1.f && sT[4] == 0.f && sT[5] == 1.f &&
                     sT[6] == -5.f && sT[7] == 1.f && sT[8] == 0.f);

    // ---- per-lane 16 steps ----
    const int o = h * 32 + lane;                    // owner 0..63 within row
    const float4* em = emS + r * EM_F4_PER_ROW + o; // access em[(3g+u)*64]
    int4 c4 = ((const int4*)codesS)[r * 64 + o];
    if (h == 0 && lane == 0) c4.x &= ~4;            // step 0 = init, not a transition

    // ptag = tag at (chunk start - 1); lane0 reads smem byte, others shfl
    unsigned prevw = __shfl_up_sync(0xffffffffu, (unsigned)c4.w, 1);
    int ptag;
    if (lane == 0) {
        const unsigned char* cbp = (const unsigned char*)codesS;
        int bi = r * 1024 + h * 512;
        ptag = (h ? cbp[bi - 1] : cbp[bi]) & 3;
    } else {
        ptag = (int)((prevw >> 24) & 3u);
    }

    float M00 = 1.f, M01 = 0.f, M02 = 0.f;
    float M10 = 0.f, M11 = 1.f, M12 = 0.f;
    float M20 = 0.f, M21 = 0.f, M22 = 1.f;
    float gold = 0.f;
    int esum = 0;

    float4 e0a = em[0 * 64],  e0b = em[1 * 64],  e0c = em[2 * 64];
    float4 e1a = em[3 * 64],  e1b = em[4 * 64],  e1c = em[5 * 64];
    float4 e2a = em[6 * 64],  e2b = em[7 * 64],  e2c = em[8 * 64];
    float4 e3a = em[9 * 64],  e3b = em[10 * 64], e3c = em[11 * 64];

    if (fastpath) {
        GROUP_FAST(e0a, e0b, e0c, (unsigned)c4.x);
        GROUP_FAST(e1a, e1b, e1c, (unsigned)c4.y);
        RENORM();
        GROUP_FAST(e2a, e2b, e2c, (unsigned)c4.z);
        GROUP_FAST(e3a, e3b, e3c, (unsigned)c4.w);
        RENORM();
    } else {
        float E00 = __expf(sT[0]), E01 = __expf(sT[1]), E02 = __expf(sT[2]);
        float E10 = __expf(sT[3]), E11 = __expf(sT[4]), E12 = __expf(sT[5]);
        float E20 = __expf(sT[6]), E21 = __expf(sT[7]), E22 = __expf(sT[8]);
        GROUP_GEN(e0a, e0b, e0c, (unsigned)c4.x);
        RENORM();
        GROUP_GEN(e1a, e1b, e1c, (unsigned)c4.y);
        RENORM();
        GROUP_GEN(e2a, e2b, e2c, (unsigned)c4.z);
        RENORM();
        GROUP_GEN(e3a, e3b, e3c, (unsigned)c4.w);
        RENORM();
    }

    // ---- in-warp ordered tree product over the 32 lane chunks ----
    float e = (float)esum;
    #pragma unroll
    for (int s = 1; s < 32; s <<= 1) {
        float Q00 = __shfl_down_sync(0xffffffffu, M00, s);
        float Q01 = __shfl_down_sync(0xffffffffu, M01, s);
        float Q02 = __shfl_down_sync(0xffffffffu, M02, s);
        float Q10 = __shfl_down_sync(0xffffffffu, M10, s);
        float Q11 = __shfl_down_sync(0xffffffffu, M11, s);
        float Q12 = __shfl_down_sync(0xffffffffu, M12, s);
        float Q20 = __shfl_down_sync(0xffffffffu, M20, s);
        float Q21 = __shfl_down_sync(0xffffffffu, M21, s);
        float Q22 = __shfl_down_sync(0xffffffffu, M22, s);
        float eq  = __shfl_down_sync(0xffffffffu, e,   s);
        float gq  = __shfl_down_sync(0xffffffffu, gold, s);

        float q00 = fmaf(M02, Q20, fmaf(M01, Q10, M00 * Q00));
        float q01 = fmaf(M02, Q21, fmaf(M01, Q11, M00 * Q01));
        float q02 = fmaf(M02, Q22, fmaf(M01, Q12, M00 * Q02));
        float q10 = fmaf(M12, Q20, fmaf(M11, Q10, M10 * Q00));
        float q11 = fmaf(M12, Q21, fmaf(M11, Q11, M10 * Q01));
        float q12 = fmaf(M12, Q22, fmaf(M11, Q12, M10 * Q02));
        float q20 = fmaf(M22, Q20, fmaf(M21, Q10, M20 * Q00));
        float q21 = fmaf(M22, Q21, fmaf(M21, Q11, M20 * Q01));
        float q22 = fmaf(M22, Q22, fmaf(M21, Q12, M20 * Q02));

        float mxa = fmaxf(fmaxf(q00, q01), q02);
        float mxb = fmaxf(fmaxf(q10, q11), q12);
        float mxc = fmaxf(fmaxf(q20, q21), q22);
        float mx  = fmaxf(fmaxf(mxa, mxb), mxc);
        int ex = (__float_as_int(mx) >> 23) - 127;
        float sc = __int_as_float((127 - ex) << 23);
        M00 = q00 * sc; M01 = q01 * sc; M02 = q02 * sc;
        M10 = q10 * sc; M11 = q11 * sc; M12 = q12 * sc;
        M20 = q20 * sc; M21 = q21 * sc; M22 = q22 * sc;

        e += eq + (float)ex;
        gold += gq;
    }

    if (lane == 0) {
        float* dst = sHalf[w];
        dst[0] = M00; dst[1] = M01; dst[2] = M02;
        dst[3] = M10; dst[4] = M11; dst[5] = M12;
        dst[6] = M20; dst[7] = M21; dst[8] = M22;
        dst[9] = e;   dst[10] = gold;
    }
    __syncthreads();

    // ---- per-row: alpha0 * H0 * H1, logZ, gold base term ----
    if (tid < RPB) {
        int rr = tid;
        const float* A  = sHalf[rr * 2];
        const float* Bm = sHalf[rr * 2 + 1];

        float4 e0 = emS[rr * EM_F4_PER_ROW];      // em[row][0][0..2]
        float a0 = __expf(e0.x), a1 = __expf(e0.y), a2 = __expf(e0.z);
        float u0 = fmaf(a2, A[6], fmaf(a1, A[3], a0 * A[0]));
        float u1 = fmaf(a2, A[7], fmaf(a1, A[4], a0 * A[1]));
        float u2 = fmaf(a2, A[8], fmaf(a1, A[5], a0 * A[2]));
        float v0 = fmaf(u2, Bm[6], fmaf(u1, Bm[3], u0 * Bm[0]));
        float v1 = fmaf(u2, Bm[7], fmaf(u1, Bm[4], u0 * Bm[1]));
        float v2 = fmaf(u2, Bm[8], fmaf(u1, Bm[5], u0 * Bm[2]));

        float esumT = A[9] + Bm[9];
        float goldT = A[10] + Bm[10];

        unsigned c0 = codesS[rr * 256];
        int   t0 = (int)(c0 & 3u);
        float m0 = (float)((c0 >> 2) & 1u);
        float em0t = (t0 == 0) ? e0.x : ((t0 == 1) ? e0.y : e0.z);
        goldT += m0 * em0t;

        float logZ = __logf(v0 + v1 + v2) + esumT * LN2F;
        srow[rr] = logZ - goldT;
    }
    __syncthreads();

    if (tid == 0) {
        g_partials[blockIdx.x] = (srow[0] + srow[1]) + (srow[2] + srow[3]);
        __threadfence();
        int tk = atomicAdd(&g_count, 1);
        sLast = (tk == NBLOCKS - 1);
    }
    __syncthreads();

    // ---- last block: fixed-order final reduction ----
    if (sLast) {
        float s = 0.f;
        #pragma unroll
        for (int i = 0; i < NBLOCKS / THREADS; ++i)
            s += __ldcg(&g_partials[tid * (NBLOCKS / THREADS) + i]);
        float* red = (float*)smem;                // reuse staging smem
        red[tid] = s;
        __syncthreads();
        #pragma unroll
        for (int st = THREADS / 2; st > 0; st >>= 1) {
            if (tid < st) red[tid] += red[tid + st];
            __syncthreads();
        }
        if (tid == 0) {
            out[0] = red[0] * (1.0f / (float)B_DIM);
            g_count = 0;                          // reset for next graph replay
        }
    }
}

extern "C" void kernel_launch(void* const* d_in, const int* in_sizes, int n_in,
                              void* d_out, int out_size)
{
    const float* emissions   = (const float*)d_in[0];
    const float* mask        = (const float*)d_in[1];
    const float* transitions = (const float*)d_in[2];
    const int*   tags        = (const int*)d_in[3];
    float* out = (float*)d_out;

    cudaFuncSetAttribute(crf_main_kernel,
                         cudaFuncAttributeMaxDynamicSharedMemorySize, SMEM_BYTES);
    crf_main_kernel<<<NBLOCKS, THREADS, SMEM_BYTES>>>(emissions, mask, transitions,
                                                      tags, out);
}

// round 7
// speedup vs baseline: 1.7755x; 1.7755x over previous
#include <cuda_runtime.h>
#include <cstdint>

// LinearCRF: out = mean_b( logZ_b - gold_b )
// 256 threads/block, 4 rows/block, 2 warps per row, lane = 16 steps.
// cp.async staging into transposed conflict-free smem; tags+mask packed
// to 1 byte/step. Linear-domain 3x3 transfer matrices, exact pow2 renorm.
// Runtime-guarded fast path for the reference transition matrix
// (unit-diagonal E, immediate FMAs); generic fallback for other inputs.
// Register-disciplined: interleaved group loads, forced 4 blocks/SM.

#define B_DIM   8192
#define L_DIM   1024
#define RPB     4
#define THREADS 256
#define NBLOCKS (B_DIM / RPB)      // 2048
#define LN2F 0.69314718055994530942f
#define AF 2.71828182845904523536f     // e^1
#define BF 0.00673794699908546710f     // e^-5

#define EM_F4_PER_ROW 768
#define SMEM_BYTES (RPB * EM_F4_PER_ROW * 16 + RPB * 256 * 4)

__device__ float g_partials[NBLOCKS];
__device__ int   g_count = 0;

__device__ __forceinline__ void cp16(uint32_t saddr, const void* gaddr) {
    asm volatile("cp.async.cg.shared.global [%0], [%1], 16;" :: "r"(saddr), "l"(gaddr));
}

// ---------- FAST path: E = [[1,a,b],[a,1,a],[b,a,1]], T in {0,1,-5} ----------
#define STEP_FAST_U(e0v, e1v, e2v, cbv) do {                                \
    float w0 = __expf(e0v), w1 = __expf(e1v), w2 = __expf(e2v);             \
    float s0 = M00 + M02, s1 = M10 + M12, s2 = M20 + M22;                   \
    float P00 = fmaf(AF, M01, fmaf(BF, M02, M00));                          \
    float P01 = fmaf(AF, s0, M01);                                          \
    float P02 = fmaf(BF, M00, fmaf(AF, M01, M02));                          \
    float P10 = fmaf(AF, M11, fmaf(BF, M12, M10));                          \
    float P11 = fmaf(AF, s1, M11);                                          \
    float P12 = fmaf(BF, M10, fmaf(AF, M11, M12));                          \
    float P20 = fmaf(AF, M21, fmaf(BF, M22, M20));                          \
    float P21 = fmaf(AF, s2, M21);                                          \
    float P22 = fmaf(BF, M20, fmaf(AF, M21, M22));                          \
    M00 = P00 * w0; M01 = P01 * w1; M02 = P02 * w2;                         \
    M10 = P10 * w0; M11 = P11 * w1; M12 = P12 * w2;                         \
    M20 = P20 * w0; M21 = P21 * w1; M22 = P22 * w2;                         \
    int tgl = (int)((cbv) & 3u);                                            \
    float etg = (tgl == 0) ? (e0v) : ((tgl == 1) ? (e1v) : (e2v));          \
    float tr  = (ptag == tgl) ? 0.f : ((ptag + tgl == 2) ? -5.f : 1.f);     \
    gold += tr + etg;                                                       \
    ptag = tgl;                                                             \
} while (0)

#define STEP_FAST_M(e0v, e1v, e2v, cbv) do {                                \
    unsigned cb_ = (cbv) & 0xffu;                                           \
    float w0 = __expf(e0v), w1 = __expf(e1v), w2 = __expf(e2v);             \
    float s0 = M00 + M02, s1 = M10 + M12, s2 = M20 + M22;                   \
    float P00 = fmaf(AF, M01, fmaf(BF, M02, M00));                          \
    float P01 = fmaf(AF, s0, M01);                                          \
    float P02 = fmaf(BF, M00, fmaf(AF, M01, M02));                          \
    float P10 = fmaf(AF, M11, fmaf(BF, M12, M10));                          \
    float P11 = fmaf(AF, s1, M11);                                          \
    float P12 = fmaf(BF, M10, fmaf(AF, M11, M12));                          \
    float P20 = fmaf(AF, M21, fmaf(BF, M22, M20));                          \
    float P21 = fmaf(AF, s2, M21);                                          \
    float P22 = fmaf(BF, M20, fmaf(AF, M21, M22));                          \
    bool u = cb_ >= 4u;                                                     \
    M00 = u ? P00 * w0 : M00; M01 = u ? P01 * w1 : M01;                     \
    M02 = u ? P02 * w2 : M02;                                               \
    M10 = u ? P10 * w0 : M10; M11 = u ? P11 * w1 : M11;                     \
    M12 = u ? P12 * w2 : M12;                                               \
    M20 = u ? P20 * w0 : M20; M21 = u ? P21 * w1 : M21;                     \
    M22 = u ? P22 * w2 : M22;                                               \
    int tgl = (int)(cb_ & 3u);                                              \
    float etg = (tgl == 0) ? (e0v) : ((tgl == 1) ? (e1v) : (e2v));          \
    float tr  = (ptag == tgl) ? 0.f : ((ptag + tgl == 2) ? -5.f : 1.f);     \
    gold += u ? (tr + etg) : 0.f;                                           \
    ptag = tgl;                                                             \
} while (0)

#define GROUP_FAST(Ea, Eb, Ec, CW) do {                                     \
    if (((CW) & 0x04040404u) == 0x04040404u) {                              \
        STEP_FAST_U(Ea.x, Ea.y, Ea.z, (CW));                                \
        STEP_FAST_U(Ea.w, Eb.x, Eb.y, (CW) >> 8);                           \
        STEP_FAST_U(Eb.z, Eb.w, Ec.x, (CW) >> 16);                          \
        STEP_FAST_U(Ec.y, Ec.z, Ec.w, (CW) >> 24);                          \
    } else {                                                                \
        STEP_FAST_M(Ea.x, Ea.y, Ea.z, (CW));                                \
        STEP_FAST_M(Ea.w, Eb.x, Eb.y, (CW) >> 8);                           \
        STEP_FAST_M(Eb.z, Eb.w, Ec.x, (CW) >> 16);                          \
        STEP_FAST_M(Ec.y, Ec.z, Ec.w, (CW) >> 24);                          \
    }                                                                       \
} while (0)

// ---------- generic fallback ----------
#define STEP_GEN(e0v, e1v, e2v, cbv) do {                                   \
    unsigned cb_ = (cbv) & 0xffu;                                           \
    float w0 = __expf(e0v), w1 = __expf(e1v), w2 = __expf(e2v);             \
    float F00 = E00 * w0, F01 = E01 * w1, F02 = E02 * w2;                   \
    float F10 = E10 * w0, F11 = E11 * w1, F12 = E12 * w2;                   \
    float F20 = E20 * w0, F21 = E21 * w1, F22 = E22 * w2;                   \
    float n00 = fmaf(M02, F20, fmaf(M01, F10, M00 * F00));                  \
    float n01 = fmaf(M02, F21, fmaf(M01, F11, M00 * F01));                  \
    float n02 = fmaf(M02, F22, fmaf(M01, F12, M00 * F02));                  \
    float n10 = fmaf(M12, F20, fmaf(M11, F10, M10 * F00));                  \
    float n11 = fmaf(M12, F21, fmaf(M11, F11, M10 * F01));                  \
    float n12 = fmaf(M12, F22, fmaf(M11, F12, M10 * F02));                  \
    float n20 = fmaf(M22, F20, fmaf(M21, F10, M20 * F00));                  \
    float n21 = fmaf(M22, F21, fmaf(M21, F11, M20 * F01));                  \
    float n22 = fmaf(M22, F22, fmaf(M21, F12, M20 * F02));                  \
    bool u = cb_ >= 4u;                                                     \
    M00 = u ? n00 : M00; M01 = u ? n01 : M01; M02 = u ? n02 : M02;          \
    M10 = u ? n10 : M10; M11 = u ? n11 : M11; M12 = u ? n12 : M12;          \
    M20 = u ? n20 : M20; M21 = u ? n21 : M21; M22 = u ? n22 : M22;          \
    int tgl = (int)(cb_ & 3u);                                              \
    float etg = (tgl == 0) ? (e0v) : ((tgl == 1) ? (e1v) : (e2v));          \
    float add = sT[ptag * 3 + tgl] + etg;                                   \
    gold += u ? add : 0.f;                                                  \
    ptag = tgl;                                                             \
} while (0)

#define GROUP_GEN(Ea, Eb, Ec, CW) do {                                      \
    STEP_GEN(Ea.x, Ea.y, Ea.z, (CW));                                       \
    STEP_GEN(Ea.w, Eb.x, Eb.y, (CW) >> 8);                                  \
    STEP_GEN(Eb.z, Eb.w, Ec.x, (CW) >> 16);                                 \
    STEP_GEN(Ec.y, Ec.z, Ec.w, (CW) >> 24);                                 \
} while (0)

#define RENORM() do {                                                       \
    float mxa = fmaxf(fmaxf(M00, M01), M02);                                \
    float mxb = fmaxf(fmaxf(M10, M11), M12);                                \
    float mxc = fmaxf(fmaxf(M20, M21), M22);                                \
    float mx  = fmaxf(fmaxf(mxa, mxb), mxc);                                \
    int ex = (__float_as_int(mx) >> 23) - 127;                              \
    float sc = __int_as_float((127 - ex) << 23);                            \
    M00 *= sc; M01 *= sc; M02 *= sc;                                        \
    M10 *= sc; M11 *= sc; M12 *= sc;                                        \
    M20 *= sc; M21 *= sc; M22 *= sc;                                        \
    esum += ex;                                                             \
} while (0)

__global__ void __launch_bounds__(THREADS, 4)
crf_main_kernel(const float* __restrict__ emissions,
                const float* __restrict__ mask,
                const float* __restrict__ transitions,
                const int*   __restrict__ tags,
                float* __restrict__ out)
{
    extern __shared__ char smem[];
    float4*   emS    = (float4*)smem;
    unsigned* codesS = (unsigned*)(smem + RPB * EM_F4_PER_ROW * 16);
    __shared__ float sT[9];
    __shared__ float sHalf[8][11];
    __shared__ float srow[RPB];
    __shared__ int   sLast;

    const int tid  = threadIdx.x;
    const int lane = tid & 31;
    const int w    = tid >> 5;      // 0..7
    const int r    = w >> 1;        // local row
    const int h    = w & 1;         // half
    const int row0 = blockIdx.x * RPB;

    if (tid < 9) sT[tid] = transitions[tid];

    uint32_t emS_a = (uint32_t)__cvta_generic_to_shared(emS);

    // ---- stage emissions: gmem-linear f4 -> smem transposed (j*64 + owner) ----
    const float4* emG = (const float4*)emissions + (size_t)row0 * 768;
    #pragma unroll
    for (int rr = 0; rr < RPB; ++rr) {
        #pragma unroll
        for (int i = 0; i < 3; ++i) {
            int k = tid + i * THREADS;              // 0..767
            int o = k / 12, j = k - o * 12;
            cp16(emS_a + (uint32_t)((rr * EM_F4_PER_ROW + j * 64 + o) << 4),
                 emG + (size_t)rr * 768 + k);
        }
    }
    asm volatile("cp.async.commit_group;");

    // ---- pack tags+mask into code bytes ----
    const int4*   tgG = (const int4*)tags + (size_t)row0 * 256;
    const float4* mkG = (const float4*)mask + (size_t)row0 * 256;
    #pragma unroll
    for (int rr = 0; rr < RPB; ++rr) {
        int4   tg = tgG[(size_t)rr * 256 + tid];
        float4 mk = mkG[(size_t)rr * 256 + tid];
        unsigned cw = ((unsigned)(tg.x & 3) | (mk.x > 0.f ? 4u : 0u))
                    | (((unsigned)(tg.y & 3) | (mk.y > 0.f ? 4u : 0u)) << 8)
                    | (((unsigned)(tg.z & 3) | (mk.z > 0.f ? 4u : 0u)) << 16)
                    | (((unsigned)(tg.w & 3) | (mk.w > 0.f ? 4u : 0u)) << 24);
        codesS[rr * 256 + tid] = cw;
    }
    asm volatile("cp.async.wait_group 0;");
    __syncthreads();

    bool fastpath = (sT[0] == 0.f && sT[1] == 1.f && sT[2] == -5.f &&
                     sT[3] == 1.f && sT[4] == 0.f && sT[5] == 1.f &&
                     sT[6] == -5.f && sT[7] == 1.f && sT[8] == 0.f);

    // ---- per-lane 16 steps ----
    const int o = h * 32 + lane;                    // owner 0..63 within row
    const float4* em = emS + r * EM_F4_PER_ROW + o; // access em[(3g+u)*64]
    int4 c4 = ((const int4*)codesS)[r * 64 + o];
    if (h == 0 && lane == 0) c4.x &= ~4;            // step 0 = init, not a transition

    unsigned prevw = __shfl_up_sync(0xffffffffu, (unsigned)c4.w, 1);
    int ptag;
    if (lane == 0) {
        const unsigned char* cbp = (const unsigned char*)codesS;
        int bi = r * 1024 + h * 512;
        ptag = (h ? cbp[bi - 1] : cbp[bi]) & 3;
    } else {
        ptag = (int)((prevw >> 24) & 3u);
    }

    float M00 = 1.f, M01 = 0.f, M02 = 0.f;
    float M10 = 0.f, M11 = 1.f, M12 = 0.f;
    float M20 = 0.f, M21 = 0.f, M22 = 1.f;
    float gold = 0.f;
    int esum = 0;

    if (fastpath) {
        // interleaved loads: at most 2 groups of float4 live at once
        float4 eAa = em[0 * 64], eAb = em[1 * 64], eAc = em[2 * 64];
        float4 eBa = em[3 * 64], eBb = em[4 * 64], eBc = em[5 * 64];
        GROUP_FAST(eAa, eAb, eAc, (unsigned)c4.x);
        eAa = em[6 * 64]; eAb = em[7 * 64]; eAc = em[8 * 64];
        GROUP_FAST(eBa, eBb, eBc, (unsigned)c4.y);
        RENORM();
        eBa = em[9 * 64]; eBb = em[10 * 64]; eBc = em[11 * 64];
        GROUP_FAST(eAa, eAb, eAc, (unsigned)c4.z);
        GROUP_FAST(eBa, eBb, eBc, (unsigned)c4.w);
        RENORM();
    } else {
        float E00 = __expf(sT[0]), E01 = __expf(sT[1]), E02 = __expf(sT[2]);
        float E10 = __expf(sT[3]), E11 = __expf(sT[4]), E12 = __expf(sT[5]);
        float E20 = __expf(sT[6]), E21 = __expf(sT[7]), E22 = __expf(sT[8]);
        float4 eAa = em[0 * 64], eAb = em[1 * 64], eAc = em[2 * 64];
        float4 eBa = em[3 * 64], eBb = em[4 * 64], eBc = em[5 * 64];
        GROUP_GEN(eAa, eAb, eAc, (unsigned)c4.x);
        RENORM();
        eAa = em[6 * 64]; eAb = em[7 * 64]; eAc = em[8 * 64];
        GROUP_GEN(eBa, eBb, eBc, (unsigned)c4.y);
        RENORM();
        eBa = em[9 * 64]; eBb = em[10 * 64]; eBc = em[11 * 64];
        GROUP_GEN(eAa, eAb, eAc, (unsigned)c4.z);
        RENORM();
        GROUP_GEN(eBa, eBb, eBc, (unsigned)c4.w);
        RENORM();
    }

    // ---- in-warp ordered tree product over the 32 lane chunks ----
    float e = (float)esum;
    #pragma unroll
    for (int s = 1; s < 32; s <<= 1) {
        float Q00 = __shfl_down_sync(0xffffffffu, M00, s);
        float Q01 = __shfl_down_sync(0xffffffffu, M01, s);
        float Q02 = __shfl_down_sync(0xffffffffu, M02, s);
        float Q10 = __shfl_down_sync(0xffffffffu, M10, s);
        float Q11 = __shfl_down_sync(0xffffffffu, M11, s);
        float Q12 = __shfl_down_sync(0xffffffffu, M12, s);
        float Q20 = __shfl_down_sync(0xffffffffu, M20, s);
        float Q21 = __shfl_down_sync(0xffffffffu, M21, s);
        float Q22 = __shfl_down_sync(0xffffffffu, M22, s);
        float eq  = __shfl_down_sync(0xffffffffu, e,   s);
        float gq  = __shfl_down_sync(0xffffffffu, gold, s);

        float q00 = fmaf(M02, Q20, fmaf(M01, Q10, M00 * Q00));
        float q01 = fmaf(M02, Q21, fmaf(M01, Q11, M00 * Q01));
        float q02 = fmaf(M02, Q22, fmaf(M01, Q12, M00 * Q02));
        float q10 = fmaf(M12, Q20, fmaf(M11, Q10, M10 * Q00));
        float q11 = fmaf(M12, Q21, fmaf(M11, Q11, M10 * Q01));
        float q12 = fmaf(M12, Q22, fmaf(M11, Q12, M10 * Q02));
        float q20 = fmaf(M22, Q20, fmaf(M21, Q10, M20 * Q00));
        float q21 = fmaf(M22, Q21, fmaf(M21, Q11, M20 * Q01));
        float q22 = fmaf(M22, Q22, fmaf(M21, Q12, M20 * Q02));

        float mxa = fmaxf(fmaxf(q00, q01), q02);
        float mxb = fmaxf(fmaxf(q10, q11), q12);
        float mxc = fmaxf(fmaxf(q20, q21), q22);
        float mx  = fmaxf(fmaxf(mxa, mxb), mxc);
        int ex = (__float_as_int(mx) >> 23) - 127;
        float sc = __int_as_float((127 - ex) << 23);
        M00 = q00 * sc; M01 = q01 * sc; M02 = q02 * sc;
        M10 = q10 * sc; M11 = q11 * sc; M12 = q12 * sc;
        M20 = q20 * sc; M21 = q21 * sc; M22 = q22 * sc;

        e += eq + (float)ex;
        gold += gq;
    }

    if (lane == 0) {
        float* dst = sHalf[w];
        dst[0] = M00; dst[1] = M01; dst[2] = M02;
        dst[3] = M10; dst[4] = M11; dst[5] = M12;
        dst[6] = M20; dst[7] = M21; dst[8] = M22;
        dst[9] = e;   dst[10] = gold;
    }
    __syncthreads();

    // ---- per-row: alpha0 * H0 * H1, logZ, gold base term ----
    if (tid < RPB) {
        int rr = tid;
        const float* A  = sHalf[rr * 2];
        const float* Bm = sHalf[rr * 2 + 1];

        float4 e0 = emS[rr * EM_F4_PER_ROW];      // em[row][0][0..2]
        float a0 = __expf(e0.x), a1 = __expf(e0.y), a2 = __expf(e0.z);
        float u0 = fmaf(a2, A[6], fmaf(a1, A[3], a0 * A[0]));
        float u1 = fmaf(a2, A[7], fmaf(a1, A[4], a0 * A[1]));
        float u2 = fmaf(a2, A[8], fmaf(a1, A[5], a0 * A[2]));
        float v0 = fmaf(u2, Bm[6], fmaf(u1, Bm[3], u0 * Bm[0]));
        float v1 = fmaf(u2, Bm[7], fmaf(u1, Bm[4], u0 * Bm[1]));
        float v2 = fmaf(u2, Bm[8], fmaf(u1, Bm[5], u0 * Bm[2]));

        float esumT = A[9] + Bm[9];
        float goldT = A[10] + Bm[10];

        unsigned c0 = codesS[rr * 256];
        int   t0 = (int)(c0 & 3u);
        float m0 = (float)((c0 >> 2) & 1u);
        float em0t = (t0 == 0) ? e0.x : ((t0 == 1) ? e0.y : e0.z);
        goldT += m0 * em0t;

        float logZ = __logf(v0 + v1 + v2) + esumT * LN2F;
        srow[rr] = logZ - goldT;
    }
    __syncthreads();

    if (tid == 0) {
        g_partials[blockIdx.x] = (srow[0] + srow[1]) + (srow[2] + srow[3]);
        __threadfence();
        int tk = atomicAdd(&g_count, 1);
        sLast = (tk == NBLOCKS - 1);
    }
    __syncthreads();

    // ---- last block: fixed-order final reduction ----
    if (sLast) {
        float s = 0.f;
        #pragma unroll
        for (int i = 0; i < NBLOCKS / THREADS; ++i)
            s += __ldcg(&g_partials[tid * (NBLOCKS / THREADS) + i]);
        float* red = (float*)smem;                // reuse staging smem
        red[tid] = s;
        __syncthreads();
        #pragma unroll
        for (int st = THREADS / 2; st > 0; st >>= 1) {
            if (tid < st) red[tid] += red[tid + st];
            __syncthreads();
        }
        if (tid == 0) {
            out[0] = red[0] * (1.0f / (float)B_DIM);
            g_count = 0;                          // reset for next graph replay
        }
    }
}

extern "C" void kernel_launch(void* const* d_in, const int* in_sizes, int n_in,
                              void* d_out, int out_size)
{
    const float* emissions   = (const float*)d_in[0];
    const float* mask        = (const float*)d_in[1];
    const float* transitions = (const float*)d_in[2];
    const int*   tags        = (const int*)d_in[3];
    float* out = (float*)d_out;

    cudaFuncSetAttribute(crf_main_kernel,
                         cudaFuncAttributeMaxDynamicSharedMemorySize, SMEM_BYTES);
    crf_main_kernel<<<NBLOCKS, THREADS, SMEM_BYTES>>>(emissions, mask, transitions,
                                                      tags, out);
}